// round 7
// baseline (speedup 1.0000x reference)
#include <cuda_runtime.h>
#include <cuda_bf16.h>
#include <math.h>
#include <stdint.h>

// Problem constants
#define NB 16
#define NA 1024
#define NT 512
#define ND 256
#define TWO_D 512

// ---------------- scratch (no allocations allowed) ----------------
__device__ float g_art[2][NB * NA * ND];
__device__ float g_tpl[2][NB * NT * ND];
__device__ __nv_bfloat16 g_art_h[2][NB * NA * ND];
__device__ __nv_bfloat16 g_art_m[2][NB * NA * ND];
__device__ __nv_bfloat16 g_tpl_h[2][NB * NT * ND];
__device__ __nv_bfloat16 g_tpl_m[2][NB * NT * ND];
__device__ __nv_bfloat16 g_wth[10 * 3 * TWO_D * ND];
__device__ __nv_bfloat16 g_wtm[10 * 3 * TWO_D * ND];
__device__ float g_a2[NB * NA];
__device__ float g_t2[NB * NT];
__device__ float g_rowmax[NB * NA];
__device__ int g_ctr[16];

#define RB_JOBS 768          // 192 tiles x 4 pair-blocks
#define RB_GRID 296          // 148 SMs x 2 CTAs

// ---------------- helpers ----------------
__device__ __forceinline__ uint32_t smem_u32(const void* p) {
    uint32_t a;
    asm("{ .reg .u64 t; cvta.to.shared.u64 t, %1; cvt.u32.u64 %0, t; }" : "=r"(a) : "l"(p));
    return a;
}
__device__ __forceinline__ void bsplit(float x, __nv_bfloat16& h, __nv_bfloat16& m) {
    h = __float2bfloat16(x);
    m = __float2bfloat16(x - __bfloat162float(h));
}
__device__ __forceinline__ void ldsm4(uint32_t a, uint32_t* r) {
    asm volatile("ldmatrix.sync.aligned.m8n8.x4.shared.b16 {%0,%1,%2,%3}, [%4];"
                 : "=r"(r[0]), "=r"(r[1]), "=r"(r[2]), "=r"(r[3]) : "r"(a));
}
__device__ __forceinline__ void mma16816(float* c, const uint32_t* a, uint32_t b0, uint32_t b1) {
    asm volatile(
        "mma.sync.aligned.m16n8k16.row.col.f32.bf16.bf16.f32 "
        "{%0,%1,%2,%3}, {%4,%5,%6,%7}, {%8,%9}, {%0,%1,%2,%3};"
        : "+f"(c[0]), "+f"(c[1]), "+f"(c[2]), "+f"(c[3])
        : "r"(a[0]), "r"(a[1]), "r"(a[2]), "r"(a[3]), "r"(b0), "r"(b1));
}
__device__ __forceinline__ void cpasync16(uint32_t dst, const void* src, uint32_t sz) {
    asm volatile("cp.async.cg.shared.global [%0], [%1], 16, %2;"
                 :: "r"(dst), "l"(src), "r"(sz));
}

// ---------------- embedding gather (f32 + hi/mid bf16) ----------------
__global__ void gather_kernel(const int* __restrict__ words,
                              const float* __restrict__ emb,
                              float* __restrict__ outf,
                              __nv_bfloat16* __restrict__ outh,
                              __nv_bfloat16* __restrict__ outm, int nrows) {
    int idx = blockIdx.x * blockDim.x + threadIdx.x;
    int total = nrows * (ND / 4);
    if (idx >= total) return;
    int row = idx >> 6;
    int d4  = idx & 63;
    int w = words[row];
    float4 v = reinterpret_cast<const float4*>(emb)[(size_t)w * 64 + d4];
    size_t o = (size_t)row * ND + d4 * 4;
    *reinterpret_cast<float4*>(outf + o) = v;
    __nv_bfloat16 h0, h1, h2, h3, m0, m1, m2, m3;
    bsplit(v.x, h0, m0); bsplit(v.y, h1, m1); bsplit(v.z, h2, m2); bsplit(v.w, h3, m3);
    *reinterpret_cast<__nv_bfloat162*>(outh + o)     = __halves2bfloat162(h0, h1);
    *reinterpret_cast<__nv_bfloat162*>(outh + o + 2) = __halves2bfloat162(h2, h3);
    *reinterpret_cast<__nv_bfloat162*>(outm + o)     = __halves2bfloat162(m0, m1);
    *reinterpret_cast<__nv_bfloat162*>(outm + o + 2) = __halves2bfloat162(m2, m3);
}

// ---------------- weight transpose + split ----------------
__global__ void wconv_kernel(const float* __restrict__ exp_w, const float* __restrict__ ref_w,
                             __nv_bfloat16* __restrict__ wh, __nv_bfloat16* __restrict__ wm) {
    __shared__ float t[32][33];
    int lk = blockIdx.x;
    int d0 = blockIdx.y * 32;
    int c0 = blockIdx.z * 32;
    const float* src = (lk < 21) ? exp_w + (size_t)lk * (ND * TWO_D)
                                 : ref_w + (size_t)(lk - 21) * (ND * TWO_D);
    t[threadIdx.y][threadIdx.x] = src[(size_t)(d0 + threadIdx.y) * TWO_D + c0 + threadIdx.x];
    __syncthreads();
    float v = t[threadIdx.x][threadIdx.y];
    size_t o = ((size_t)lk * TWO_D + c0 + threadIdx.y) * ND + d0 + threadIdx.x;
    __nv_bfloat16 h, m;
    bsplit(v, h, m);
    wh[o] = h;
    wm[o] = m;
}

// ---------------- persistent mma.sync res-block ----------------
// Jobs 0..767: x = j>>2 (0..191, <128 article else template), y = j&3 (pair block).
// CTA tile 128 rows x 64 GLU pairs, B rows interleaved (even=a, odd=g).
// 8 warps = 2M(64) x 4N(32). K-stage 32, 24 stages, 3-ring, 1 sync/stage.
#define RB_STAGE 32768  // Ah 8K | Am 8K | Bh 8K | Bm 8K
#define RB_SMEM  98304  // 3 stages

__global__ __launch_bounds__(256, 2)
void resblock_mma(const float* __restrict__ ArtF,
                  const __nv_bfloat16* __restrict__ ArtH, const __nv_bfloat16* __restrict__ ArtM,
                  float* __restrict__ ArtOF, __nv_bfloat16* __restrict__ ArtOH,
                  __nv_bfloat16* __restrict__ ArtOM,
                  const float* __restrict__ TplF,
                  const __nv_bfloat16* __restrict__ TplH, const __nv_bfloat16* __restrict__ TplM,
                  float* __restrict__ TplOF, __nv_bfloat16* __restrict__ TplOH,
                  __nv_bfloat16* __restrict__ TplOM,
                  const __nv_bfloat16* __restrict__ Wth, const __nv_bfloat16* __restrict__ Wtm,
                  const float* __restrict__ bias, int dil, int* __restrict__ ctr) {
    extern __shared__ char smem[];
    __shared__ int sjob;
    const uint32_t sb = smem_u32(smem);
    const int tid = threadIdx.x;
    const int lane = tid & 31;
    const int wid = tid >> 5;

    const int warpM = (wid & 1) * 64;
    const int warpN = (wid >> 1) * 32;

    // job-independent fragment addressing
    uint32_t offA[4];
    int swzA[4];
    {
        int r15 = lane & 15;
#pragma unroll
        for (int mt = 0; mt < 4; mt++) {
            int r = warpM + mt * 16 + r15;
            offA[mt] = r * 64;
            swzA[mt] = (r >> 1) & 3;
        }
    }
    const int cbA = lane >> 4;
    uint32_t offB[2];
    int swzB[2];
    const int jm = lane >> 3;
    const int cbB = jm & 1;
    {
        int rb = (jm >> 1) * 8 + (lane & 7);
#pragma unroll
        for (int nt = 0; nt < 2; nt++) {
            int r = warpN + nt * 16 + rb;
            offB[nt] = r * 64;
            swzB[nt] = (r >> 1) & 3;
        }
    }

    for (;;) {
        __syncthreads();                       // protect sjob + smem reuse
        if (tid == 0) sjob = atomicAdd(ctr, 1);
        __syncthreads();
        const int job = sjob;
        if (job >= RB_JOBS) break;

        const int x = job >> 2;
        const bool isA = x < 128;
        const int mb = isA ? x : (x - 128);
        const int L = isA ? NA : NT;
        const __nv_bfloat16* Xh = isA ? ArtH : TplH;
        const __nv_bfloat16* Xm = isA ? ArtM : TplM;
        const float* Xf = isA ? ArtF : TplF;
        float* Yf = isA ? ArtOF : TplOF;
        __nv_bfloat16* Yh = isA ? ArtOH : TplOH;
        __nv_bfloat16* Ym = isA ? ArtOM : TplOM;

        const int rowBase = mb * 128;
        const int pairBase = (job & 3) * 64;
        const int bb = rowBase / L;
        const int lBase = rowBase - bb * L;

        float acc[4][4][4];
#pragma unroll
        for (int i = 0; i < 4; i++)
#pragma unroll
            for (int j = 0; j < 4; j++)
#pragma unroll
                for (int q = 0; q < 4; q++) acc[i][j][q] = 0.f;

        auto issue = [&](int s) {
            if (s < 24) {
                const int buf = s - (s / 3) * 3;
                const uint32_t base = sb + buf * RB_STAGE;
                const int tap = s >> 3;
                const int k0 = (s & 7) << 5;
                const int shift = (tap - 1) * dil;
#pragma unroll
                for (int q = 0; q < 2; q++) {
                    int idx = tid + q * 256;
                    int row = idx >> 2;
                    int kc = idx & 3;
                    int kcs = kc ^ ((row >> 1) & 3);
                    uint32_t dst = base + row * 64 + kcs * 16;
                    int p = lBase + row + shift;
                    uint32_t sz = (p >= 0 && p < L) ? 16u : 0u;
                    int pc = p < 0 ? 0 : (p >= L ? L - 1 : p);
                    size_t aoff = (size_t)(bb * L + pc) * ND + k0 + kc * 8;
                    cpasync16(dst, Xh + aoff, sz);
                    cpasync16(dst + 8192, Xm + aoff, sz);
                    int pr = pairBase + (row >> 1);
                    int chan = (row & 1) ? (256 + pr) : pr;
                    size_t boff = ((size_t)tap * TWO_D + chan) * ND + k0 + kc * 8;
                    cpasync16(dst + 16384, Wth + boff, 16u);
                    cpasync16(dst + 24576, Wtm + boff, 16u);
                }
            }
            asm volatile("cp.async.commit_group;");
        };

        auto domma = [&](int buf) {
            const uint32_t base = sb + buf * RB_STAGE;
            uint32_t bh[2][4], bm[2][4];
            uint32_t ah[2][4], am[2][4];
#pragma unroll
            for (int h = 0; h < 2; h++) {
#pragma unroll
                for (int nt = 0; nt < 2; nt++) {
                    uint32_t a = base + offB[nt] + (uint32_t)(((cbB + 2 * h) ^ swzB[nt]) * 16);
                    ldsm4(a + 16384, bh[nt]);
                    ldsm4(a + 24576, bm[nt]);
                }
                {
                    uint32_t a = base + offA[0] + (uint32_t)(((cbA + 2 * h) ^ swzA[0]) * 16);
                    ldsm4(a, ah[0]);
                    ldsm4(a + 8192, am[0]);
                }
                int cur = 0;
#pragma unroll
                for (int mt = 0; mt < 4; mt++) {
                    int nxt = cur ^ 1;
                    if (mt < 3) {
                        uint32_t a = base + offA[mt + 1] +
                                     (uint32_t)(((cbA + 2 * h) ^ swzA[mt + 1]) * 16);
                        ldsm4(a, ah[nxt]);
                        ldsm4(a + 8192, am[nxt]);
                    }
                    mma16816(acc[mt][0], ah[cur], bh[0][0], bh[0][1]);
                    mma16816(acc[mt][1], ah[cur], bh[0][2], bh[0][3]);
                    mma16816(acc[mt][2], ah[cur], bh[1][0], bh[1][1]);
                    mma16816(acc[mt][3], ah[cur], bh[1][2], bh[1][3]);
                    mma16816(acc[mt][0], ah[cur], bm[0][0], bm[0][1]);
                    mma16816(acc[mt][1], ah[cur], bm[0][2], bm[0][3]);
                    mma16816(acc[mt][2], ah[cur], bm[1][0], bm[1][1]);
                    mma16816(acc[mt][3], ah[cur], bm[1][2], bm[1][3]);
                    mma16816(acc[mt][0], am[cur], bh[0][0], bh[0][1]);
                    mma16816(acc[mt][1], am[cur], bh[0][2], bh[0][3]);
                    mma16816(acc[mt][2], am[cur], bh[1][0], bh[1][1]);
                    mma16816(acc[mt][3], am[cur], bh[1][2], bh[1][3]);
                    cur = nxt;
                }
            }
        };

        issue(0);
        issue(1);
        int buf = 0;
        for (int s = 0; s < 24; s++) {
            asm volatile("cp.async.wait_group 1;");
            __syncthreads();
            issue(s + 2);
            domma(buf);
            buf = (buf == 2) ? 0 : buf + 1;
        }

        // ---- in-register epilogue ----
        {
            const int laneRow = lane >> 2;
            const int laneP = lane & 3;
            const int pB = pairBase + (warpN >> 1) + laneP;
#pragma unroll
            for (int nj = 0; nj < 4; nj++) {
                const int p = pB + nj * 4;
                const float ba = bias[p];
                const float bg = bias[256 + p];
#pragma unroll
                for (int mt = 0; mt < 4; mt++) {
                    const int r0 = rowBase + warpM + mt * 16 + laneRow;
                    const float* c = acc[mt][nj];
#pragma unroll
                    for (int hrow = 0; hrow < 2; hrow++) {
                        const size_t o = (size_t)(r0 + 8 * hrow) * ND + p;
                        float a = c[2 * hrow] + ba;
                        float g = c[2 * hrow + 1] + bg;
                        float y = Xf[o] + a * (1.f / (1.f + expf(-g)));
                        Yf[o] = y;
                        __nv_bfloat16 hh, mm;
                        bsplit(y, hh, mm);
                        Yh[o] = hh;
                        Ym[o] = mm;
                    }
                }
            }
        }
    }
}

// ---------------- squared norms per row ----------------
__global__ void norm_kernel(const float* __restrict__ X, float* __restrict__ out) {
    int row = blockIdx.x;
    int tid = threadIdx.x;
    float4 v = reinterpret_cast<const float4*>(X + (size_t)row * ND)[tid];
    float s = v.x * v.x + v.y * v.y + v.z * v.z + v.w * v.w;
#pragma unroll
    for (int off = 16; off > 0; off >>= 1)
        s += __shfl_down_sync(0xFFFFFFFFu, s, off);
    __shared__ float ws[2];
    if ((tid & 31) == 0) ws[tid >> 5] = s;
    __syncthreads();
    if (tid == 0) out[row] = ws[0] + ws[1];
}

// ---------------- tensorized distance + row-max ----------------
#define DI_STAGE 32768
#define DI_SMEM  98304

__global__ __launch_bounds__(256)
void dist_mma(const __nv_bfloat16* __restrict__ Ah_, const __nv_bfloat16* __restrict__ Am_,
              const __nv_bfloat16* __restrict__ Th_, const __nv_bfloat16* __restrict__ Tm_,
              const float* __restrict__ a2, const float* __restrict__ t2,
              const float* __restrict__ amask, const float* __restrict__ tmask,
              float* __restrict__ rowmax_out) {
    extern __shared__ char smem[];
    __shared__ int rmax[128];
    __shared__ float st2[128], stm[128];
    const uint32_t sb = smem_u32(smem);
    const int tid = threadIdx.x;
    const int lane = tid & 31;
    const int wid = tid >> 5;

    const int b = blockIdx.y;
    const int rowBase = blockIdx.x * 128;

    if (tid < 128) rmax[tid] = 0;

    const int warpM = (wid & 1) * 64;
    const int warpN = (wid >> 1) * 32;

    uint32_t offA[4];
    int swzA[4];
    {
        int r15 = lane & 15;
#pragma unroll
        for (int mt = 0; mt < 4; mt++) {
            int r = warpM + mt * 16 + r15;
            offA[mt] = r * 64;
            swzA[mt] = (r >> 1) & 3;
        }
    }
    const int cbA = lane >> 4;
    uint32_t offB[2];
    int swzB[2];
    const int jm = lane >> 3;
    const int cbB = jm & 1;
    {
        int rb = (jm >> 1) * 8 + (lane & 7);
#pragma unroll
        for (int nt = 0; nt < 2; nt++) {
            int r = warpN + nt * 16 + rb;
            offB[nt] = r * 64;
            swzB[nt] = (r >> 1) & 3;
        }
    }

    float a2v[4][2], amv[4][2];
    float tmax[4][2];
#pragma unroll
    for (int mt = 0; mt < 4; mt++)
#pragma unroll
        for (int h = 0; h < 2; h++) {
            int r = rowBase + warpM + mt * 16 + (lane >> 2) + 8 * h;
            a2v[mt][h] = a2[b * NA + r];
            amv[mt][h] = amask[b * NA + r];
            tmax[mt][h] = 0.f;
        }

    for (int tc = 0; tc < 2; tc++) {
        const int tBase = (blockIdx.z * 2 + tc) * 128;

        if (tid < 128) {
            st2[tid] = t2[b * NT + tBase + tid];
            stm[tid] = tmask[b * NT + tBase + tid];
        }

        float acc[4][4][4];
#pragma unroll
        for (int i = 0; i < 4; i++)
#pragma unroll
            for (int j = 0; j < 4; j++)
#pragma unroll
                for (int q = 0; q < 4; q++) acc[i][j][q] = 0.f;

        auto issue = [&](int s) {
            if (s < 8) {
                const int buf = s - (s / 3) * 3;
                const uint32_t base = sb + buf * DI_STAGE;
                const int k0 = s << 5;
#pragma unroll
                for (int q = 0; q < 2; q++) {
                    int idx = tid + q * 256;
                    int row = idx >> 2;
                    int kc = idx & 3;
                    int kcs = kc ^ ((row >> 1) & 3);
                    uint32_t dst = base + row * 64 + kcs * 16;
                    size_t aoff = (size_t)(b * NA + rowBase + row) * ND + k0 + kc * 8;
                    cpasync16(dst, Ah_ + aoff, 16u);
                    cpasync16(dst + 8192, Am_ + aoff, 16u);
                    size_t toff = (size_t)(b * NT + tBase + row) * ND + k0 + kc * 8;
                    cpasync16(dst + 16384, Th_ + toff, 16u);
                    cpasync16(dst + 24576, Tm_ + toff, 16u);
                }
            }
            asm volatile("cp.async.commit_group;");
        };

        auto domma = [&](int buf) {
            const uint32_t base = sb + buf * DI_STAGE;
            uint32_t bh[2][4], bm[2][4];
            uint32_t ah[2][4], am[2][4];
#pragma unroll
            for (int h = 0; h < 2; h++) {
#pragma unroll
                for (int nt = 0; nt < 2; nt++) {
                    uint32_t a = base + offB[nt] + (uint32_t)(((cbB + 2 * h) ^ swzB[nt]) * 16);
                    ldsm4(a + 16384, bh[nt]);
                    ldsm4(a + 24576, bm[nt]);
                }
                {
                    uint32_t a = base + offA[0] + (uint32_t)(((cbA + 2 * h) ^ swzA[0]) * 16);
                    ldsm4(a, ah[0]);
                    ldsm4(a + 8192, am[0]);
                }
                int cur = 0;
#pragma unroll
                for (int mt = 0; mt < 4; mt++) {
                    int nxt = cur ^ 1;
                    if (mt < 3) {
                        uint32_t a = base + offA[mt + 1] +
                                     (uint32_t)(((cbA + 2 * h) ^ swzA[mt + 1]) * 16);
                        ldsm4(a, ah[nxt]);
                        ldsm4(a + 8192, am[nxt]);
                    }
                    mma16816(acc[mt][0], ah[cur], bh[0][0], bh[0][1]);
                    mma16816(acc[mt][1], ah[cur], bh[0][2], bh[0][3]);
                    mma16816(acc[mt][2], ah[cur], bh[1][0], bh[1][1]);
                    mma16816(acc[mt][3], ah[cur], bh[1][2], bh[1][3]);
                    mma16816(acc[mt][0], ah[cur], bm[0][0], bm[0][1]);
                    mma16816(acc[mt][1], ah[cur], bm[0][2], bm[0][3]);
                    mma16816(acc[mt][2], ah[cur], bm[1][0], bm[1][1]);
                    mma16816(acc[mt][3], ah[cur], bm[1][2], bm[1][3]);
                    mma16816(acc[mt][0], am[cur], bh[0][0], bh[0][1]);
                    mma16816(acc[mt][1], am[cur], bh[0][2], bh[0][3]);
                    mma16816(acc[mt][2], am[cur], bh[1][0], bh[1][1]);
                    mma16816(acc[mt][3], am[cur], bh[1][2], bh[1][3]);
                    cur = nxt;
                }
            }
        };

        issue(0);
        issue(1);
        int buf = 0;
        for (int s = 0; s < 8; s++) {
            asm volatile("cp.async.wait_group 1;");
            __syncthreads();
            issue(s + 2);
            domma(buf);
            buf = (buf == 2) ? 0 : buf + 1;
        }

        const int colL = warpN + 2 * (lane & 3);
#pragma unroll
        for (int mt = 0; mt < 4; mt++)
#pragma unroll
            for (int h = 0; h < 2; h++) {
                float best = tmax[mt][h];
                const float a2r = a2v[mt][h];
                const float amr = amv[mt][h];
#pragma unroll
                for (int nj = 0; nj < 4; nj++) {
#pragma unroll
                    for (int cc = 0; cc < 2; cc++) {
                        int cl = colL + nj * 8 + cc;
                        float d = a2r + st2[cl] - 2.f * acc[mt][nj][2 * h + cc];
                        d = fmaxf(d, 0.f);
                        best = fmaxf(best, expf(-d) * stm[cl] * amr);
                    }
                }
                tmax[mt][h] = best;
            }
        __syncthreads();
    }

#pragma unroll
    for (int mt = 0; mt < 4; mt++)
#pragma unroll
        for (int h = 0; h < 2; h++) {
            float v = tmax[mt][h];
            v = fmaxf(v, __shfl_xor_sync(0xFFFFFFFFu, v, 1));
            v = fmaxf(v, __shfl_xor_sync(0xFFFFFFFFu, v, 2));
            if ((lane & 3) == 0)
                atomicMax(&rmax[warpM + mt * 16 + (lane >> 2) + 8 * h], __float_as_int(v));
        }
    __syncthreads();
    if (tid < 128)
        atomicMax(reinterpret_cast<int*>(rowmax_out) + b * NA + rowBase + tid, rmax[tid]);
}

// ---------------- top-10 + MLP ----------------
__global__ void topk_mlp_kernel(const float* __restrict__ rowmax,
                                const float* __restrict__ ff1w,
                                const float* __restrict__ ff1b,
                                const float* __restrict__ ff2w,
                                const float* __restrict__ ff2b,
                                float* __restrict__ out) {
    int b = blockIdx.x;
    __shared__ float vals[NA];
    __shared__ float sv[256];
    __shared__ int si[256];
    __shared__ float top[10];
    int tid = threadIdx.x;
#pragma unroll
    for (int q = 0; q < 4; q++) vals[tid + q * 256] = rowmax[b * NA + tid + q * 256];
    __syncthreads();
    for (int it = 0; it < 10; it++) {
        float best = -1.f;
        int bi = 0;
        for (int i = tid; i < NA; i += 256) {
            if (vals[i] > best) { best = vals[i]; bi = i; }
        }
        sv[tid] = best;
        si[tid] = bi;
        __syncthreads();
        for (int off = 128; off > 0; off >>= 1) {
            if (tid < off) {
                if (sv[tid + off] > sv[tid]) { sv[tid] = sv[tid + off]; si[tid] = si[tid + off]; }
            }
            __syncthreads();
        }
        if (tid == 0) { top[it] = sv[0]; vals[si[0]] = -1.f; }
        __syncthreads();
    }
    if (tid == 0) {
        float o = ff2b[0];
        for (int j = 0; j < 10; j++) {
            float h = ff1b[j];
            for (int i = 0; i < 10; i++) h += top[i] * ff1w[i * 10 + j];
            h = fmaxf(h, 0.f);
            o += h * ff2w[j];
        }
        out[b] = o;
    }
}

// ---------------- launcher ----------------
extern "C" void kernel_launch(void* const* d_in, const int* in_sizes, int n_in,
                              void* d_out, int out_size) {
    const int* art_w   = (const int*)d_in[0];
    const int* tpl_w   = (const int*)d_in[2];
    const float* am    = (const float*)d_in[4];
    const float* tm    = (const float*)d_in[5];
    const float* emb   = (const float*)d_in[6];
    const float* exp_w = (const float*)d_in[7];
    const float* exp_b = (const float*)d_in[8];
    const float* ref_w = (const float*)d_in[9];
    const float* ref_b = (const float*)d_in[10];
    const float* ff1w  = (const float*)d_in[11];
    const float* ff1b  = (const float*)d_in[12];
    const float* ff2w  = (const float*)d_in[13];
    const float* ff2b  = (const float*)d_in[14];

    float *artf, *tplf, *a2p, *t2p, *rmp;
    __nv_bfloat16 *arth, *artm, *tplh, *tplm, *wth, *wtm;
    int* ctrp;
    cudaGetSymbolAddress((void**)&artf, g_art);
    cudaGetSymbolAddress((void**)&tplf, g_tpl);
    cudaGetSymbolAddress((void**)&arth, g_art_h);
    cudaGetSymbolAddress((void**)&artm, g_art_m);
    cudaGetSymbolAddress((void**)&tplh, g_tpl_h);
    cudaGetSymbolAddress((void**)&tplm, g_tpl_m);
    cudaGetSymbolAddress((void**)&wth, g_wth);
    cudaGetSymbolAddress((void**)&wtm, g_wtm);
    cudaGetSymbolAddress((void**)&a2p, g_a2);
    cudaGetSymbolAddress((void**)&t2p, g_t2);
    cudaGetSymbolAddress((void**)&rmp, g_rowmax);
    cudaGetSymbolAddress((void**)&ctrp, g_ctr);

    const size_t ASZ = (size_t)NB * NA * ND;
    const size_t TSZ = (size_t)NB * NT * ND;
    float* af[2] = {artf, artf + ASZ};
    float* tf[2] = {tplf, tplf + TSZ};
    __nv_bfloat16* ah[2] = {arth, arth + ASZ};
    __nv_bfloat16* amid[2] = {artm, artm + ASZ};
    __nv_bfloat16* th[2] = {tplh, tplh + TSZ};
    __nv_bfloat16* tmid[2] = {tplm, tplm + TSZ};

    cudaFuncSetAttribute(resblock_mma, cudaFuncAttributeMaxDynamicSharedMemorySize, RB_SMEM);
    cudaFuncSetAttribute(dist_mma, cudaFuncAttributeMaxDynamicSharedMemorySize, DI_SMEM);

    cudaMemsetAsync(ctrp, 0, 16 * sizeof(int));
    wconv_kernel<<<dim3(30, 8, 16), dim3(32, 32)>>>(exp_w, ref_w, wth, wtm);
    gather_kernel<<<(NB * NA * 64 + 255) / 256, 256>>>(art_w, emb, af[0], ah[0], amid[0], NB * NA);
    gather_kernel<<<(NB * NT * 64 + 255) / 256, 256>>>(tpl_w, emb, tf[0], th[0], tmid[0], NB * NT);

    const int dils[10] = {1, 2, 4, 8, 16, 32, 32, 1, 1, 1};
    int cur = 0;
    for (int i = 0; i < 10; i++) {
        const __nv_bfloat16* wh = wth + (size_t)i * 3 * TWO_D * ND;
        const __nv_bfloat16* wm = wtm + (size_t)i * 3 * TWO_D * ND;
        const float* bias = (i < 7) ? exp_b + (size_t)i * TWO_D
                                    : ref_b + (size_t)(i - 7) * TWO_D;
        resblock_mma<<<RB_GRID, 256, RB_SMEM>>>(
            af[cur], ah[cur], amid[cur], af[1 - cur], ah[1 - cur], amid[1 - cur],
            tf[cur], th[cur], tmid[cur], tf[1 - cur], th[1 - cur], tmid[1 - cur],
            wh, wm, bias, dils[i], ctrp + i);
        cur ^= 1;
    }
    // 10 flips -> final tensors back in buffer 0

    norm_kernel<<<NB * NA, 64>>>(af[cur], a2p);
    norm_kernel<<<NB * NT, 64>>>(tf[cur], t2p);

    cudaMemsetAsync(rmp, 0, NB * NA * sizeof(float));
    dist_mma<<<dim3(NA / 128, NB, 2), 256, DI_SMEM>>>(
        ah[cur], amid[cur], th[cur], tmid[cur], a2p, t2p, am, tm, rmp);

    topk_mlp_kernel<<<NB, 256>>>(rmp, ff1w, ff1b, ff2w, ff2b, (float*)d_out);
}

// round 9
// speedup vs baseline: 1.3971x; 1.3971x over previous
#include <cuda_runtime.h>
#include <cuda_bf16.h>
#include <math.h>
#include <stdint.h>

// Problem constants
#define NB 16
#define NA 1024
#define NT 512
#define ND 256
#define TWO_D 512

// ---------------- scratch (no allocations allowed) ----------------
__device__ float g_art[2][NB * NA * ND];
__device__ float g_tpl[2][NB * NT * ND];
__device__ __nv_bfloat16 g_art_h[2][NB * NA * ND];
__device__ __nv_bfloat16 g_art_m[2][NB * NA * ND];
__device__ __nv_bfloat16 g_tpl_h[2][NB * NT * ND];
__device__ __nv_bfloat16 g_tpl_m[2][NB * NT * ND];
__device__ __nv_bfloat16 g_wth[10 * 3 * TWO_D * ND];
__device__ __nv_bfloat16 g_wtm[10 * 3 * TWO_D * ND];
__device__ float g_a2[NB * NA];
__device__ float g_t2[NB * NT];
__device__ float g_rowmax[NB * NA];

// ---------------- helpers ----------------
__device__ __forceinline__ uint32_t smem_u32(const void* p) {
    uint32_t a;
    asm("{ .reg .u64 t; cvta.to.shared.u64 t, %1; cvt.u32.u64 %0, t; }" : "=r"(a) : "l"(p));
    return a;
}
__device__ __forceinline__ void bsplit(float x, __nv_bfloat16& h, __nv_bfloat16& m) {
    h = __float2bfloat16(x);
    m = __float2bfloat16(x - __bfloat162float(h));
}
__device__ __forceinline__ void ldsm4(uint32_t a, uint32_t* r) {
    asm volatile("ldmatrix.sync.aligned.m8n8.x4.shared.b16 {%0,%1,%2,%3}, [%4];"
                 : "=r"(r[0]), "=r"(r[1]), "=r"(r[2]), "=r"(r[3]) : "r"(a));
}
__device__ __forceinline__ void mma16816(float* c, const uint32_t* a, uint32_t b0, uint32_t b1) {
    asm volatile(
        "mma.sync.aligned.m16n8k16.row.col.f32.bf16.bf16.f32 "
        "{%0,%1,%2,%3}, {%4,%5,%6,%7}, {%8,%9}, {%0,%1,%2,%3};"
        : "+f"(c[0]), "+f"(c[1]), "+f"(c[2]), "+f"(c[3])
        : "r"(a[0]), "r"(a[1]), "r"(a[2]), "r"(a[3]), "r"(b0), "r"(b1));
}
__device__ __forceinline__ void cpasync16(uint32_t dst, const void* src, uint32_t sz) {
    asm volatile("cp.async.cg.shared.global [%0], [%1], 16, %2;"
                 :: "r"(dst), "l"(src), "r"(sz));
}

// ---------------- embedding gather (f32 + hi/mid bf16) ----------------
__global__ void gather_kernel(const int* __restrict__ words,
                              const float* __restrict__ emb,
                              float* __restrict__ outf,
                              __nv_bfloat16* __restrict__ outh,
                              __nv_bfloat16* __restrict__ outm, int nrows) {
    int idx = blockIdx.x * blockDim.x + threadIdx.x;
    int total = nrows * (ND / 4);
    if (idx >= total) return;
    int row = idx >> 6;
    int d4  = idx & 63;
    int w = words[row];
    float4 v = reinterpret_cast<const float4*>(emb)[(size_t)w * 64 + d4];
    size_t o = (size_t)row * ND + d4 * 4;
    *reinterpret_cast<float4*>(outf + o) = v;
    __nv_bfloat16 h0, h1, h2, h3, m0, m1, m2, m3;
    bsplit(v.x, h0, m0); bsplit(v.y, h1, m1); bsplit(v.z, h2, m2); bsplit(v.w, h3, m3);
    *reinterpret_cast<__nv_bfloat162*>(outh + o)     = __halves2bfloat162(h0, h1);
    *reinterpret_cast<__nv_bfloat162*>(outh + o + 2) = __halves2bfloat162(h2, h3);
    *reinterpret_cast<__nv_bfloat162*>(outm + o)     = __halves2bfloat162(m0, m1);
    *reinterpret_cast<__nv_bfloat162*>(outm + o + 2) = __halves2bfloat162(m2, m3);
}

// ---------------- weight transpose + split ----------------
__global__ void wconv_kernel(const float* __restrict__ exp_w, const float* __restrict__ ref_w,
                             __nv_bfloat16* __restrict__ wh, __nv_bfloat16* __restrict__ wm) {
    __shared__ float t[32][33];
    int lk = blockIdx.x;
    int d0 = blockIdx.y * 32;
    int c0 = blockIdx.z * 32;
    const float* src = (lk < 21) ? exp_w + (size_t)lk * (ND * TWO_D)
                                 : ref_w + (size_t)(lk - 21) * (ND * TWO_D);
    t[threadIdx.y][threadIdx.x] = src[(size_t)(d0 + threadIdx.y) * TWO_D + c0 + threadIdx.x];
    __syncthreads();
    float v = t[threadIdx.x][threadIdx.y];
    size_t o = ((size_t)lk * TWO_D + c0 + threadIdx.y) * ND + d0 + threadIdx.x;
    __nv_bfloat16 h, m;
    bsplit(v, h, m);
    wh[o] = h;
    wm[o] = m;
}

// ---------------- mma.sync res-block v5 (static grid + phase stagger) ----------------
// CTA 128 rows x 64 GLU pairs, B rows interleaved (even=a, odd=g) -> register GLU.
// 8 warps = 2M(64) x 4N(32). K-stage 32, 24 stages, 3-ring, 1 sync/stage.
// Stagger: co-resident CTA pairs process stages rotated by 12 to de-phase barriers.
// Loader issue placed between the two k16 halves of each stage's mma work.
#define RB_STAGE 32768  // Ah 8K | Am 8K | Bh 8K | Bm 8K
#define RB_SMEM  98304  // 3 stages

__global__ __launch_bounds__(256, 2)
void resblock_mma(const float* __restrict__ ArtF,
                  const __nv_bfloat16* __restrict__ ArtH, const __nv_bfloat16* __restrict__ ArtM,
                  float* __restrict__ ArtOF, __nv_bfloat16* __restrict__ ArtOH,
                  __nv_bfloat16* __restrict__ ArtOM,
                  const float* __restrict__ TplF,
                  const __nv_bfloat16* __restrict__ TplH, const __nv_bfloat16* __restrict__ TplM,
                  float* __restrict__ TplOF, __nv_bfloat16* __restrict__ TplOH,
                  __nv_bfloat16* __restrict__ TplOM,
                  const __nv_bfloat16* __restrict__ Wth, const __nv_bfloat16* __restrict__ Wtm,
                  const float* __restrict__ bias, int dil) {
    extern __shared__ char smem[];
    const uint32_t sb = smem_u32(smem);
    const int tid = threadIdx.x;
    const int lane = tid & 31;
    const int wid = tid >> 5;

    const bool isA = blockIdx.x < 128;
    const int mb = isA ? blockIdx.x : (blockIdx.x - 128);
    const int L = isA ? NA : NT;
    const __nv_bfloat16* Xh = isA ? ArtH : TplH;
    const __nv_bfloat16* Xm = isA ? ArtM : TplM;
    const float* Xf = isA ? ArtF : TplF;
    float* Yf = isA ? ArtOF : TplOF;
    __nv_bfloat16* Yh = isA ? ArtOH : TplOH;
    __nv_bfloat16* Ym = isA ? ArtOM : TplOM;

    const int rowBase = mb * 128;
    const int pairBase = blockIdx.y * 64;
    const int bb = rowBase / L;
    const int lBase = rowBase - bb * L;

    // co-resident CTAs (linear bids ~148 apart) get opposite rotation
    const int linBid = blockIdx.x + gridDim.x * blockIdx.y;
    const int rot = ((linBid / 148) & 1) * 12;

    const int warpM = (wid & 1) * 64;
    const int warpN = (wid >> 1) * 32;

    uint32_t offA[4];
    int swzA[4];
    {
        int r15 = lane & 15;
#pragma unroll
        for (int mt = 0; mt < 4; mt++) {
            int r = warpM + mt * 16 + r15;
            offA[mt] = r * 64;
            swzA[mt] = (r >> 1) & 3;
        }
    }
    const int cbA = lane >> 4;
    uint32_t offB[2];
    int swzB[2];
    const int jm = lane >> 3;
    const int cbB = jm & 1;
    {
        int rb = (jm >> 1) * 8 + (lane & 7);
#pragma unroll
        for (int nt = 0; nt < 2; nt++) {
            int r = warpN + nt * 16 + rb;
            offB[nt] = r * 64;
            swzB[nt] = (r >> 1) & 3;
        }
    }

    float acc[4][4][4];
#pragma unroll
    for (int i = 0; i < 4; i++)
#pragma unroll
        for (int j = 0; j < 4; j++)
#pragma unroll
            for (int q = 0; q < 4; q++) acc[i][j][q] = 0.f;

    // i = pipeline position (ring buffer index i%3); stage = (i + rot) % 24
    auto issue = [&](int i) {
        if (i < 24) {
            const int s = (i + rot) % 24;
            const uint32_t base = sb + (i - (i / 3) * 3) * RB_STAGE;
            const int tap = s >> 3;
            const int k0 = (s & 7) << 5;
            const int shift = (tap - 1) * dil;
#pragma unroll
            for (int q = 0; q < 2; q++) {
                int idx = tid + q * 256;
                int row = idx >> 2;
                int kc = idx & 3;
                int kcs = kc ^ ((row >> 1) & 3);
                uint32_t dst = base + row * 64 + kcs * 16;
                int p = lBase + row + shift;
                uint32_t sz = (p >= 0 && p < L) ? 16u : 0u;
                int pc = p < 0 ? 0 : (p >= L ? L - 1 : p);
                size_t aoff = (size_t)(bb * L + pc) * ND + k0 + kc * 8;
                cpasync16(dst, Xh + aoff, sz);
                cpasync16(dst + 8192, Xm + aoff, sz);
                int pr = pairBase + (row >> 1);
                int chan = (row & 1) ? (256 + pr) : pr;
                size_t boff = ((size_t)tap * TWO_D + chan) * ND + k0 + kc * 8;
                cpasync16(dst + 16384, Wth + boff, 16u);
                cpasync16(dst + 24576, Wtm + boff, 16u);
            }
        }
        asm volatile("cp.async.commit_group;");
    };

    // one k16 half of a stage's mma work
    auto domma_half = [&](int buf, int h) {
        const uint32_t base = sb + buf * RB_STAGE;
        uint32_t bh[2][4], bm[2][4];
        uint32_t ah[2][4], am[2][4];
#pragma unroll
        for (int nt = 0; nt < 2; nt++) {
            uint32_t a = base + offB[nt] + (uint32_t)(((cbB + 2 * h) ^ swzB[nt]) * 16);
            ldsm4(a + 16384, bh[nt]);
            ldsm4(a + 24576, bm[nt]);
        }
        {
            uint32_t a = base + offA[0] + (uint32_t)(((cbA + 2 * h) ^ swzA[0]) * 16);
            ldsm4(a, ah[0]);
            ldsm4(a + 8192, am[0]);
        }
        int cur = 0;
#pragma unroll
        for (int mt = 0; mt < 4; mt++) {
            int nxt = cur ^ 1;
            if (mt < 3) {
                uint32_t a = base + offA[mt + 1] +
                             (uint32_t)(((cbA + 2 * h) ^ swzA[mt + 1]) * 16);
                ldsm4(a, ah[nxt]);
                ldsm4(a + 8192, am[nxt]);
            }
            mma16816(acc[mt][0], ah[cur], bh[0][0], bh[0][1]);
            mma16816(acc[mt][1], ah[cur], bh[0][2], bh[0][3]);
            mma16816(acc[mt][2], ah[cur], bh[1][0], bh[1][1]);
            mma16816(acc[mt][3], ah[cur], bh[1][2], bh[1][3]);
            mma16816(acc[mt][0], ah[cur], bm[0][0], bm[0][1]);
            mma16816(acc[mt][1], ah[cur], bm[0][2], bm[0][3]);
            mma16816(acc[mt][2], ah[cur], bm[1][0], bm[1][1]);
            mma16816(acc[mt][3], ah[cur], bm[1][2], bm[1][3]);
            mma16816(acc[mt][0], am[cur], bh[0][0], bh[0][1]);
            mma16816(acc[mt][1], am[cur], bh[0][2], bh[0][3]);
            mma16816(acc[mt][2], am[cur], bh[1][0], bh[1][1]);
            mma16816(acc[mt][3], am[cur], bh[1][2], bh[1][3]);
            cur = nxt;
        }
    };

    issue(0);
    issue(1);
    int buf = 0;
    for (int s = 0; s < 24; s++) {
        asm volatile("cp.async.wait_group 1;");
        __syncthreads();
        domma_half(buf, 0);
        issue(s + 2);          // loader burst hidden under half-0 mma stream
        domma_half(buf, 1);
        buf = (buf == 2) ? 0 : buf + 1;
    }

    // ---- in-register epilogue: bias + GLU + residual + bf16 split ----
    {
        const int laneRow = lane >> 2;
        const int laneP = lane & 3;
        const int pB = pairBase + (warpN >> 1) + laneP;
#pragma unroll
        for (int nj = 0; nj < 4; nj++) {
            const int p = pB + nj * 4;
            const float ba = bias[p];
            const float bg = bias[256 + p];
#pragma unroll
            for (int mt = 0; mt < 4; mt++) {
                const int r0 = rowBase + warpM + mt * 16 + laneRow;
                const float* c = acc[mt][nj];
#pragma unroll
                for (int hrow = 0; hrow < 2; hrow++) {
                    const size_t o = (size_t)(r0 + 8 * hrow) * ND + p;
                    float a = c[2 * hrow] + ba;
                    float g = c[2 * hrow + 1] + bg;
                    float y = Xf[o] + a * (1.f / (1.f + expf(-g)));
                    Yf[o] = y;
                    __nv_bfloat16 hh, mm;
                    bsplit(y, hh, mm);
                    Yh[o] = hh;
                    Ym[o] = mm;
                }
            }
        }
    }
}

// ---------------- squared norms per row ----------------
__global__ void norm_kernel(const float* __restrict__ X, float* __restrict__ out) {
    int row = blockIdx.x;
    int tid = threadIdx.x;
    float4 v = reinterpret_cast<const float4*>(X + (size_t)row * ND)[tid];
    float s = v.x * v.x + v.y * v.y + v.z * v.z + v.w * v.w;
#pragma unroll
    for (int off = 16; off > 0; off >>= 1)
        s += __shfl_down_sync(0xFFFFFFFFu, s, off);
    __shared__ float ws[2];
    if ((tid & 31) == 0) ws[tid >> 5] = s;
    __syncthreads();
    if (tid == 0) out[row] = ws[0] + ws[1];
}

// ---------------- tensorized distance + row-max ----------------
#define DI_STAGE 32768
#define DI_SMEM  98304

__global__ __launch_bounds__(256)
void dist_mma(const __nv_bfloat16* __restrict__ Ah_, const __nv_bfloat16* __restrict__ Am_,
              const __nv_bfloat16* __restrict__ Th_, const __nv_bfloat16* __restrict__ Tm_,
              const float* __restrict__ a2, const float* __restrict__ t2,
              const float* __restrict__ amask, const float* __restrict__ tmask,
              float* __restrict__ rowmax_out) {
    extern __shared__ char smem[];
    __shared__ int rmax[128];
    __shared__ float st2[128], stm[128];
    const uint32_t sb = smem_u32(smem);
    const int tid = threadIdx.x;
    const int lane = tid & 31;
    const int wid = tid >> 5;

    const int b = blockIdx.y;
    const int rowBase = blockIdx.x * 128;

    if (tid < 128) rmax[tid] = 0;

    const int warpM = (wid & 1) * 64;
    const int warpN = (wid >> 1) * 32;

    uint32_t offA[4];
    int swzA[4];
    {
        int r15 = lane & 15;
#pragma unroll
        for (int mt = 0; mt < 4; mt++) {
            int r = warpM + mt * 16 + r15;
            offA[mt] = r * 64;
            swzA[mt] = (r >> 1) & 3;
        }
    }
    const int cbA = lane >> 4;
    uint32_t offB[2];
    int swzB[2];
    const int jm = lane >> 3;
    const int cbB = jm & 1;
    {
        int rb = (jm >> 1) * 8 + (lane & 7);
#pragma unroll
        for (int nt = 0; nt < 2; nt++) {
            int r = warpN + nt * 16 + rb;
            offB[nt] = r * 64;
            swzB[nt] = (r >> 1) & 3;
        }
    }

    float a2v[4][2], amv[4][2];
    float tmax[4][2];
#pragma unroll
    for (int mt = 0; mt < 4; mt++)
#pragma unroll
        for (int h = 0; h < 2; h++) {
            int r = rowBase + warpM + mt * 16 + (lane >> 2) + 8 * h;
            a2v[mt][h] = a2[b * NA + r];
            amv[mt][h] = amask[b * NA + r];
            tmax[mt][h] = 0.f;
        }

    for (int tc = 0; tc < 2; tc++) {
        const int tBase = (blockIdx.z * 2 + tc) * 128;

        if (tid < 128) {
            st2[tid] = t2[b * NT + tBase + tid];
            stm[tid] = tmask[b * NT + tBase + tid];
        }

        float acc[4][4][4];
#pragma unroll
        for (int i = 0; i < 4; i++)
#pragma unroll
            for (int j = 0; j < 4; j++)
#pragma unroll
                for (int q = 0; q < 4; q++) acc[i][j][q] = 0.f;

        auto issue = [&](int s) {
            if (s < 8) {
                const int buf = s - (s / 3) * 3;
                const uint32_t base = sb + buf * DI_STAGE;
                const int k0 = s << 5;
#pragma unroll
                for (int q = 0; q < 2; q++) {
                    int idx = tid + q * 256;
                    int row = idx >> 2;
                    int kc = idx & 3;
                    int kcs = kc ^ ((row >> 1) & 3);
                    uint32_t dst = base + row * 64 + kcs * 16;
                    size_t aoff = (size_t)(b * NA + rowBase + row) * ND + k0 + kc * 8;
                    cpasync16(dst, Ah_ + aoff, 16u);
                    cpasync16(dst + 8192, Am_ + aoff, 16u);
                    size_t toff = (size_t)(b * NT + tBase + row) * ND + k0 + kc * 8;
                    cpasync16(dst + 16384, Th_ + toff, 16u);
                    cpasync16(dst + 24576, Tm_ + toff, 16u);
                }
            }
            asm volatile("cp.async.commit_group;");
        };

        auto domma = [&](int buf) {
            const uint32_t base = sb + buf * DI_STAGE;
            uint32_t bh[2][4], bm[2][4];
            uint32_t ah[2][4], am[2][4];
#pragma unroll
            for (int h = 0; h < 2; h++) {
#pragma unroll
                for (int nt = 0; nt < 2; nt++) {
                    uint32_t a = base + offB[nt] + (uint32_t)(((cbB + 2 * h) ^ swzB[nt]) * 16);
                    ldsm4(a + 16384, bh[nt]);
                    ldsm4(a + 24576, bm[nt]);
                }
                {
                    uint32_t a = base + offA[0] + (uint32_t)(((cbA + 2 * h) ^ swzA[0]) * 16);
                    ldsm4(a, ah[0]);
                    ldsm4(a + 8192, am[0]);
                }
                int cur = 0;
#pragma unroll
                for (int mt = 0; mt < 4; mt++) {
                    int nxt = cur ^ 1;
                    if (mt < 3) {
                        uint32_t a = base + offA[mt + 1] +
                                     (uint32_t)(((cbA + 2 * h) ^ swzA[mt + 1]) * 16);
                        ldsm4(a, ah[nxt]);
                        ldsm4(a + 8192, am[nxt]);
                    }
                    mma16816(acc[mt][0], ah[cur], bh[0][0], bh[0][1]);
                    mma16816(acc[mt][1], ah[cur], bh[0][2], bh[0][3]);
                    mma16816(acc[mt][2], ah[cur], bh[1][0], bh[1][1]);
                    mma16816(acc[mt][3], ah[cur], bh[1][2], bh[1][3]);
                    mma16816(acc[mt][0], ah[cur], bm[0][0], bm[0][1]);
                    mma16816(acc[mt][1], ah[cur], bm[0][2], bm[0][3]);
                    mma16816(acc[mt][2], ah[cur], bm[1][0], bm[1][1]);
                    mma16816(acc[mt][3], ah[cur], bm[1][2], bm[1][3]);
                    mma16816(acc[mt][0], am[cur], bh[0][0], bh[0][1]);
                    mma16816(acc[mt][1], am[cur], bh[0][2], bh[0][3]);
                    mma16816(acc[mt][2], am[cur], bh[1][0], bh[1][1]);
                    mma16816(acc[mt][3], am[cur], bh[1][2], bh[1][3]);
                    cur = nxt;
                }
            }
        };

        issue(0);
        issue(1);
        int buf = 0;
        for (int s = 0; s < 8; s++) {
            asm volatile("cp.async.wait_group 1;");
            __syncthreads();
            issue(s + 2);
            domma(buf);
            buf = (buf == 2) ? 0 : buf + 1;
        }

        const int colL = warpN + 2 * (lane & 3);
#pragma unroll
        for (int mt = 0; mt < 4; mt++)
#pragma unroll
            for (int h = 0; h < 2; h++) {
                float best = tmax[mt][h];
                const float a2r = a2v[mt][h];
                const float amr = amv[mt][h];
#pragma unroll
                for (int nj = 0; nj < 4; nj++) {
#pragma unroll
                    for (int cc = 0; cc < 2; cc++) {
                        int cl = colL + nj * 8 + cc;
                        float d = a2r + st2[cl] - 2.f * acc[mt][nj][2 * h + cc];
                        d = fmaxf(d, 0.f);
                        best = fmaxf(best, expf(-d) * stm[cl] * amr);
                    }
                }
                tmax[mt][h] = best;
            }
        __syncthreads();
    }

#pragma unroll
    for (int mt = 0; mt < 4; mt++)
#pragma unroll
        for (int h = 0; h < 2; h++) {
            float v = tmax[mt][h];
            v = fmaxf(v, __shfl_xor_sync(0xFFFFFFFFu, v, 1));
            v = fmaxf(v, __shfl_xor_sync(0xFFFFFFFFu, v, 2));
            if ((lane & 3) == 0)
                atomicMax(&rmax[warpM + mt * 16 + (lane >> 2) + 8 * h], __float_as_int(v));
        }
    __syncthreads();
    if (tid < 128)
        atomicMax(reinterpret_cast<int*>(rowmax_out) + b * NA + rowBase + tid, rmax[tid]);
}

// ---------------- top-10 + MLP ----------------
__global__ void topk_mlp_kernel(const float* __restrict__ rowmax,
                                const float* __restrict__ ff1w,
                                const float* __restrict__ ff1b,
                                const float* __restrict__ ff2w,
                                const float* __restrict__ ff2b,
                                float* __restrict__ out) {
    int b = blockIdx.x;
    __shared__ float vals[NA];
    __shared__ float sv[256];
    __shared__ int si[256];
    __shared__ float top[10];
    int tid = threadIdx.x;
#pragma unroll
    for (int q = 0; q < 4; q++) vals[tid + q * 256] = rowmax[b * NA + tid + q * 256];
    __syncthreads();
    for (int it = 0; it < 10; it++) {
        float best = -1.f;
        int bi = 0;
        for (int i = tid; i < NA; i += 256) {
            if (vals[i] > best) { best = vals[i]; bi = i; }
        }
        sv[tid] = best;
        si[tid] = bi;
        __syncthreads();
        for (int off = 128; off > 0; off >>= 1) {
            if (tid < off) {
                if (sv[tid + off] > sv[tid]) { sv[tid] = sv[tid + off]; si[tid] = si[tid + off]; }
            }
            __syncthreads();
        }
        if (tid == 0) { top[it] = sv[0]; vals[si[0]] = -1.f; }
        __syncthreads();
    }
    if (tid == 0) {
        float o = ff2b[0];
        for (int j = 0; j < 10; j++) {
            float h = ff1b[j];
            for (int i = 0; i < 10; i++) h += top[i] * ff1w[i * 10 + j];
            h = fmaxf(h, 0.f);
            o += h * ff2w[j];
        }
        out[b] = o;
    }
}

// ---------------- launcher ----------------
extern "C" void kernel_launch(void* const* d_in, const int* in_sizes, int n_in,
                              void* d_out, int out_size) {
    const int* art_w   = (const int*)d_in[0];
    const int* tpl_w   = (const int*)d_in[2];
    const float* am    = (const float*)d_in[4];
    const float* tm    = (const float*)d_in[5];
    const float* emb   = (const float*)d_in[6];
    const float* exp_w = (const float*)d_in[7];
    const float* exp_b = (const float*)d_in[8];
    const float* ref_w = (const float*)d_in[9];
    const float* ref_b = (const float*)d_in[10];
    const float* ff1w  = (const float*)d_in[11];
    const float* ff1b  = (const float*)d_in[12];
    const float* ff2w  = (const float*)d_in[13];
    const float* ff2b  = (const float*)d_in[14];

    float *artf, *tplf, *a2p, *t2p, *rmp;
    __nv_bfloat16 *arth, *artm, *tplh, *tplm, *wth, *wtm;
    cudaGetSymbolAddress((void**)&artf, g_art);
    cudaGetSymbolAddress((void**)&tplf, g_tpl);
    cudaGetSymbolAddress((void**)&arth, g_art_h);
    cudaGetSymbolAddress((void**)&artm, g_art_m);
    cudaGetSymbolAddress((void**)&tplh, g_tpl_h);
    cudaGetSymbolAddress((void**)&tplm, g_tpl_m);
    cudaGetSymbolAddress((void**)&wth, g_wth);
    cudaGetSymbolAddress((void**)&wtm, g_wtm);
    cudaGetSymbolAddress((void**)&a2p, g_a2);
    cudaGetSymbolAddress((void**)&t2p, g_t2);
    cudaGetSymbolAddress((void**)&rmp, g_rowmax);

    const size_t ASZ = (size_t)NB * NA * ND;
    const size_t TSZ = (size_t)NB * NT * ND;
    float* af[2] = {artf, artf + ASZ};
    float* tf[2] = {tplf, tplf + TSZ};
    __nv_bfloat16* ah[2] = {arth, arth + ASZ};
    __nv_bfloat16* amid[2] = {artm, artm + ASZ};
    __nv_bfloat16* th[2] = {tplh, tplh + TSZ};
    __nv_bfloat16* tmid[2] = {tplm, tplm + TSZ};

    cudaFuncSetAttribute(resblock_mma, cudaFuncAttributeMaxDynamicSharedMemorySize, RB_SMEM);
    cudaFuncSetAttribute(dist_mma, cudaFuncAttributeMaxDynamicSharedMemorySize, DI_SMEM);

    wconv_kernel<<<dim3(30, 8, 16), dim3(32, 32)>>>(exp_w, ref_w, wth, wtm);
    gather_kernel<<<(NB * NA * 64 + 255) / 256, 256>>>(art_w, emb, af[0], ah[0], amid[0], NB * NA);
    gather_kernel<<<(NB * NT * 64 + 255) / 256, 256>>>(tpl_w, emb, tf[0], th[0], tmid[0], NB * NT);

    const int dils[10] = {1, 2, 4, 8, 16, 32, 32, 1, 1, 1};
    int cur = 0;
    for (int i = 0; i < 10; i++) {
        const __nv_bfloat16* wh = wth + (size_t)i * 3 * TWO_D * ND;
        const __nv_bfloat16* wm = wtm + (size_t)i * 3 * TWO_D * ND;
        const float* bias = (i < 7) ? exp_b + (size_t)i * TWO_D
                                    : ref_b + (size_t)(i - 7) * TWO_D;
        resblock_mma<<<dim3(128 + 64, 4), 256, RB_SMEM>>>(
            af[cur], ah[cur], amid[cur], af[1 - cur], ah[1 - cur], amid[1 - cur],
            tf[cur], th[cur], tmid[cur], tf[1 - cur], th[1 - cur], tmid[1 - cur],
            wh, wm, bias, dils[i]);
        cur ^= 1;
    }
    // 10 flips -> final tensors back in buffer 0

    norm_kernel<<<NB * NA, 64>>>(af[cur], a2p);
    norm_kernel<<<NB * NT, 64>>>(tf[cur], t2p);

    cudaMemsetAsync(rmp, 0, NB * NA * sizeof(float));
    dist_mma<<<dim3(NA / 128, NB, 2), 256, DI_SMEM>>>(
        ah[cur], amid[cur], th[cur], tmid[cur], a2p, t2p, am, tm, rmp);

    topk_mlp_kernel<<<NB, 256>>>(rmp, ff1w, ff1b, ff2w, ff2b, (float*)d_out);
}